// round 14
// baseline (speedup 1.0000x reference)
#include <cuda_runtime.h>
#include <cstdint>

#define SQ   4096
#define EMB  1024
#define NH   16
#define HD   64

// ---------------- scratch ----------------
__device__ uint32_t g_qb [NH*SQ*HD/2];   // bf16 [h][s][d]
__device__ uint32_t g_kb [NH*SQ*HD/2];   // bf16 [h][s][d]
__device__ uint32_t g_vb [NH*HD*SQ/2];   // bf16 [h][d][s]
__device__ float    g_vF [NH*SQ*HD];     // fp32 exact V [h][s][d]
__device__ float    g_cs [NH*64*HD];     // per-64-block V colsums
__device__ float    g_vcs[NH*SQ*HD];     // inclusive cumsum over keys
__device__ uint32_t g_aHb[SQ*EMB/2];     // attention out bf16 hi
__device__ uint32_t g_aLb[SQ*EMB/2];     // attention out bf16 lo
__device__ uint32_t g_woHb[EMB*EMB/2];
__device__ uint32_t g_woLb[EMB*EMB/2];

// ---------------- helpers ----------------
__device__ __forceinline__ uint32_t s2u(const void* p) {
    uint32_t a; asm("{ .reg .u64 t; cvta.to.shared.u64 t, %1; cvt.u32.u64 %0, t; }" : "=r"(a) : "l"(p));
    return a;
}
__device__ __forceinline__ uint32_t pkbf(float lo, float hi) {   // packed bf16x2 {lo|hi<<16}
    uint32_t r; asm("cvt.rn.bf16x2.f32 %0, %1, %2;" : "=r"(r) : "f"(hi), "f"(lo));
    return r;
}
__device__ __forceinline__ float bf_of(float f) {
    uint32_t r; asm("cvt.rn.bf16x2.f32 %0, %1, %2;" : "=r"(r) : "f"(0.f), "f"(f));
    return __uint_as_float(r << 16);
}
__device__ __forceinline__ void ldm4(uint32_t r[4], uint32_t a) {
    asm volatile("ldmatrix.sync.aligned.m8n8.x4.shared.b16 {%0,%1,%2,%3}, [%4];"
                 : "=r"(r[0]), "=r"(r[1]), "=r"(r[2]), "=r"(r[3]) : "r"(a));
}
__device__ __forceinline__ void mma_bf16(float d[4], const uint32_t a[4], uint32_t b0, uint32_t b1) {
    asm volatile("mma.sync.aligned.m16n8k16.row.col.f32.bf16.bf16.f32 "
                 "{%0,%1,%2,%3},{%4,%5,%6,%7},{%8,%9},{%0,%1,%2,%3};"
                 : "+f"(d[0]), "+f"(d[1]), "+f"(d[2]), "+f"(d[3])
                 : "r"(a[0]), "r"(a[1]), "r"(a[2]), "r"(a[3]), "r"(b0), "r"(b1));
}
#define CP16(d_, s_) asm volatile("cp.async.cg.shared.global [%0], [%1], 16;" :: "r"(d_), "l"(s_))
#define CPCOMMIT()   asm volatile("cp.async.commit_group;" ::: "memory")
#define CPWAIT0()    asm volatile("cp.async.wait_group 0;" ::: "memory")

// bf16 fragment loads, parametric row stride (must be 16B-aligned, conflict-free)
__device__ __forceinline__ void ldaS(uint32_t r[4], uint32_t base, int m0, int ks, int lane, int st) {
    int g = lane >> 3, rr = lane & 7;
    uint32_t a = base + (uint32_t)(m0 + ((g & 1) << 3) + rr) * st + (uint32_t)((ks << 4) + ((g >> 1) << 3)) * 2;
    ldm4(r, a);
}
__device__ __forceinline__ void ldbS(uint32_t t[4], uint32_t base, int p, int ks, int lane, int st) {
    int g = lane >> 3, rr = lane & 7;
    uint32_t a = base + (uint32_t)(p * 16 + ((g >> 1) << 3) + rr) * st + (uint32_t)((ks << 4) + ((g & 1) << 3)) * 2;
    ldm4(t, a);
}
#define BST 144
#define ldaB(r, base, m0, ks, lane) ldaS(r, base, m0, ks, lane, BST)
#define ldbB(t, base, p, ks, lane)  ldbS(t, base, p, ks, lane, BST)

// ---------------- kernel 0: split wo into bf16 hi/lo ----------------
__global__ void wo_split_kernel(const float* __restrict__ wo) {
    int i = blockIdx.x * 256 + threadIdx.x;
    float2 w = *(const float2*)&wo[2 * i];
    float h0 = bf_of(w.x), h1 = bf_of(w.y);
    g_woHb[i] = pkbf(h0, h1);
    g_woLb[i] = pkbf(w.x - h0, w.y - h1);
}

// ---------------- kernel 0b: inclusive cumsum of V over keys (ILP restructured) ----------------
__global__ void vcs_kernel() {
    int idx = blockIdx.x * 256 + threadIdx.x;   // h(16) x blk(64) x d(64)
    int d = idx & 63, blk = (idx >> 6) & 63, h = idx >> 12;
    // prefix over block colsums: 4 independent partial accumulators
    float p0 = 0.f, p1 = 0.f, p2 = 0.f, p3 = 0.f;
    const float* cs = g_cs + (h * 64) * HD + d;
    int b = 0;
    for (; b + 4 <= blk; b += 4) {
        p0 += cs[b * HD]; p1 += cs[(b + 1) * HD];
        p2 += cs[(b + 2) * HD]; p3 += cs[(b + 3) * HD];
    }
    for (; b < blk; b++) p0 += cs[b * HD];
    float run = (p0 + p1) + (p2 + p3);
    // in-block: batch 16 independent loads, then register prefix
    int base = (h * SQ + blk * 64) * HD + d;
    #pragma unroll
    for (int c = 0; c < 64; c += 16) {
        float v[16];
        #pragma unroll
        for (int r = 0; r < 16; r++) v[r] = g_vF[base + (c + r) * HD];
        #pragma unroll
        for (int r = 0; r < 16; r++) { run += v[r]; g_vcs[base + (c + r) * HD] = run; }
    }
}

// ---------------- kernel 1: QKV projection, all bf16, 3 CTAs/SM ----------------
#define QKV_SMEM 55296
__global__ void __launch_bounds__(256, 3) qkv_kernel(
    const float* __restrict__ x,
    const float* __restrict__ wq, const float* __restrict__ wk, const float* __restrict__ wv)
{
    extern __shared__ char smc[];
    uint32_t smb = s2u(smc);
    uint32_t XhB = smb, XlB = smb + 18432, WhB = smb + 36864, WlB = smb + 46080;
    int tid = threadIdx.x, wid = tid >> 5, lane = tid & 31;
    int bx = blockIdx.x, s0 = bx * 128, h = blockIdx.y, m = blockIdx.z;
    const float* w = (m == 0 ? wq : (m == 1 ? wk : wv)) + h * 64 * 64;

    #pragma unroll
    for (int i = 0; i < 8; i++) {
        int idx = tid + 256 * i, row = idx >> 4, c4 = idx & 15;
        float4 v = *(const float4*)&x[(s0 + row) * EMB + h * 64 + c4 * 4];
        float h0 = bf_of(v.x), h1 = bf_of(v.y), h2 = bf_of(v.z), h3 = bf_of(v.w);
        *(uint2*)(smc + row * BST + c4 * 8) = make_uint2(pkbf(h0, h1), pkbf(h2, h3));
        if (m == 2)
            *(uint2*)(smc + 18432 + row * BST + c4 * 8) =
                make_uint2(pkbf(v.x - h0, v.y - h1), pkbf(v.z - h2, v.w - h3));
    }
    #pragma unroll
    for (int i = 0; i < 4; i++) {
        int idx = tid + 256 * i, row = idx >> 4, c4 = idx & 15;
        float4 v = *(const float4*)&w[row * 64 + c4 * 4];
        float h0 = bf_of(v.x), h1 = bf_of(v.y), h2 = bf_of(v.z), h3 = bf_of(v.w);
        *(uint2*)(smc + 36864 + row * BST + c4 * 8) = make_uint2(pkbf(h0, h1), pkbf(h2, h3));
        if (m == 2)
            *(uint2*)(smc + 46080 + row * BST + c4 * 8) =
                make_uint2(pkbf(v.x - h0, v.y - h1), pkbf(v.z - h2, v.w - h3));
    }
    __syncthreads();

    float o[8][4] = {};
    #pragma unroll
    for (int ks = 0; ks < 4; ks++) {
        uint32_t aa[4]; ldaB(aa, XhB, wid * 16, ks, lane);
        #pragma unroll
        for (int p = 0; p < 4; p++) {
            uint32_t t[4]; ldbB(t, WhB, p, ks, lane);
            mma_bf16(o[2 * p], aa, t[0], t[1]); mma_bf16(o[2 * p + 1], aa, t[2], t[3]);
        }
    }
    if (m == 2) {
        #pragma unroll
        for (int ks = 0; ks < 4; ks++) {
            uint32_t aa[4]; ldaB(aa, XlB, wid * 16, ks, lane);
            #pragma unroll
            for (int p = 0; p < 4; p++) {
                uint32_t t[4]; ldbB(t, WhB, p, ks, lane);
                mma_bf16(o[2 * p], aa, t[0], t[1]); mma_bf16(o[2 * p + 1], aa, t[2], t[3]);
            }
        }
        #pragma unroll
        for (int ks = 0; ks < 4; ks++) {
            uint32_t aa[4]; ldaB(aa, XhB, wid * 16, ks, lane);
            #pragma unroll
            for (int p = 0; p < 4; p++) {
                uint32_t t[4]; ldbB(t, WlB, p, ks, lane);
                mma_bf16(o[2 * p], aa, t[0], t[1]); mma_bf16(o[2 * p + 1], aa, t[2], t[3]);
            }
        }
    }

    int r = wid * 16 + (lane >> 2), c = 2 * (lane & 3);
    if (m < 2) {
        uint32_t* dst = (m == 0 ? g_qb : g_kb) + ((h * SQ + s0) * HD >> 1);
        #pragma unroll
        for (int n = 0; n < 8; n++) {
            dst[(r * HD + n * 8 + c) >> 1]       = pkbf(o[n][0], o[n][1]);
            dst[((r + 8) * HD + n * 8 + c) >> 1] = pkbf(o[n][2], o[n][3]);
        }
    } else {
        #pragma unroll
        for (int n = 0; n < 8; n++) {
            *(float2*)&g_vF[(h * SQ + s0 + r) * HD + n * 8 + c]     = make_float2(o[n][0], o[n][1]);
            *(float2*)&g_vF[(h * SQ + s0 + r + 8) * HD + n * 8 + c] = make_float2(o[n][2], o[n][3]);
        }
        __syncthreads();
        float* Vt = (float*)smc;   // [d][s], stride 132 floats
        #pragma unroll
        for (int n = 0; n < 8; n++) {
            #pragma unroll
            for (int j = 0; j < 4; j++) {
                int d = n * 8 + c + (j & 1), rr = r + ((j >> 1) << 3);
                Vt[d * 132 + rr] = o[n][j];
            }
        }
        __syncthreads();
        #pragma unroll
        for (int i = 0; i < 8; i++) {
            int idx = tid + 256 * i, d = idx >> 5, s4 = idx & 31;
            float4 v = *(float4*)&Vt[d * 132 + s4 * 4];
            *(uint2*)&g_vb[((h * HD + d) * SQ + s0 + s4 * 4) >> 1] =
                make_uint2(pkbf(v.x, v.y), pkbf(v.z, v.w));
        }
        {
            int d = tid >> 2, half = (tid >> 1) & 1, part = tid & 1;
            int sb = half * 64 + part * 32;
            float cs = 0.f;
            #pragma unroll
            for (int j = 0; j < 32; j += 4) {
                float4 a4 = *(float4*)&Vt[d * 132 + sb + j];
                cs += a4.x + a4.y + a4.z + a4.w;
            }
            cs += __shfl_xor_sync(0xffffffffu, cs, 1);
            if (part == 0) g_cs[(h * 64 + bx * 2 + half) * HD + d] = cs;
        }
    }
}

// ---------------- kernel 2: flash attention (unchanged from R13) ----------------
#define F_K0 18432
#define F_V0 36864
#define FLASH_SMEM 55296
#define ONES2 0x3F803F80u   // bf16x2 {1.0, 1.0}
#define C1X2  0x3E003E00u   // bf16x2 {0.125}
#define C2X2  0x3C003C00u   // bf16x2 {0.0078125}
__global__ void __launch_bounds__(256, 3) flash_kernel() {
    extern __shared__ char smc[];
    uint32_t smb = s2u(smc);
    int tid = threadIdx.x, wid = tid >> 5, lane = tid & 31;
    int qb = 31 - (int)blockIdx.x;
    int h = blockIdx.y;
    int kb_last = 2 * qb + 1;
    int s0 = qb * 128;

    {   // Q tile bf16 [row][d]
        const uint4* qs = (const uint4*)(g_qb + ((h * SQ + s0) * HD >> 1));
        #pragma unroll
        for (int i = 0; i < 4; i++) {
            int idx = tid + 256 * i, row = idx >> 3, c16 = idx & 7;
            *(uint4*)(smc + row * BST + c16 * 16) = qs[idx];
        }
    }
    {   // prefetch kb=0 into buffer 0
        const char* kp = (const char*)g_kb + (size_t)(h * SQ) * HD * 2;
        const char* vp = (const char*)g_vb + (size_t)(h * HD) * SQ * 2;
        #pragma unroll
        for (int i = 0; i < 2; i++) {
            int idx = tid + 256 * i, row = idx >> 3, c16 = idx & 7;
            CP16(smb + F_K0 + row * BST + c16 * 16, kp + (size_t)row * HD * 2 + c16 * 16);
            CP16(smb + F_V0 + row * BST + c16 * 16, vp + (size_t)row * SQ * 2 + c16 * 16);
        }
        CPCOMMIT();
    }
    __syncthreads();

    uint32_t qa[4][4];
    #pragma unroll
    for (int ks = 0; ks < 4; ks++) ldaB(qa[ks], smb, wid * 16, ks, lane);

    float o[8][4] = {};
    float osum[4] = {};
    int pr = wid * 16 + (lane >> 2), pc = 2 * (lane & 3);
    int rA = s0 + pr;
    const float C1 = 0.125f, C2 = 0.0078125f;

    for (int kb = 0; kb <= kb_last; kb++) {
        int cur = kb & 1;
        CPWAIT0();
        __syncthreads();
        uint32_t Kb = smb + F_K0 + cur * 9216;
        uint32_t Vb = smb + F_V0 + cur * 9216;

        if (kb < kb_last) {
            int nb = kb + 1;
            const char* kp = (const char*)g_kb + (size_t)(h * SQ + nb * 64) * HD * 2;
            const char* vp = (const char*)g_vb + ((size_t)(h * HD) * SQ + nb * 64) * 2;
            uint32_t dk = smb + F_K0 + (1 - cur) * 9216;
            uint32_t dv = smb + F_V0 + (1 - cur) * 9216;
            #pragma unroll
            for (int i = 0; i < 2; i++) {
                int idx = tid + 256 * i, row = idx >> 3, c16 = idx & 7;
                CP16(dk + row * BST + c16 * 16, kp + (size_t)row * HD * 2 + c16 * 16);
                CP16(dv + row * BST + c16 * 16, vp + (size_t)row * SQ * 2 + c16 * 16);
            }
            CPCOMMIT();
        }

        bool diag = (kb >= 2 * qb);
        #pragma unroll
        for (int h32 = 0; h32 < 2; h32++) {
            float s[4][4] = {};
            #pragma unroll
            for (int ks = 0; ks < 4; ks++) {
                #pragma unroll
                for (int pp = 0; pp < 2; pp++) {
                    uint32_t t[4]; ldbB(t, Kb, 2 * h32 + pp, ks, lane);
                    mma_bf16(s[2 * pp], qa[ks], t[0], t[1]);
                    mma_bf16(s[2 * pp + 1], qa[ks], t[2], t[3]);
                }
            }
            uint32_t Tpk[4][2];
            if (diag) {
                #pragma unroll
                for (int n = 0; n < 4; n++) {
                    #pragma unroll
                    for (int j = 0; j < 4; j++) {
                        float sv = s[n][j];
                        float T = sv * fmaf(sv, C2, C1);
                        int col = kb * 64 + h32 * 32 + n * 8 + pc + (j & 1);
                        int row = rA + ((j >> 1) << 3);
                        s[n][j] = (col <= row) ? T : 0.f;
                    }
                    Tpk[n][0] = pkbf(s[n][0], s[n][1]);
                    Tpk[n][1] = pkbf(s[n][2], s[n][3]);
                }
            } else {
                #pragma unroll
                for (int n = 0; n < 4; n++) {
                    uint32_t s2a = pkbf(s[n][0], s[n][1]);
                    uint32_t s2b = pkbf(s[n][2], s[n][3]);
                    uint32_t ua, ub;
                    asm("fma.rn.bf16x2 %0, %1, %2, %3;" : "=r"(ua) : "r"(s2a), "r"(C2X2), "r"(C1X2));
                    asm("fma.rn.bf16x2 %0, %1, %2, %3;" : "=r"(ub) : "r"(s2b), "r"(C2X2), "r"(C1X2));
                    asm("mul.rn.bf16x2 %0, %1, %2;" : "=r"(Tpk[n][0]) : "r"(s2a), "r"(ua));
                    asm("mul.rn.bf16x2 %0, %1, %2;" : "=r"(Tpk[n][1]) : "r"(s2b), "r"(ub));
                }
            }
            #pragma unroll
            for (int kk = 0; kk < 2; kk++) {
                uint32_t pa[4] = {Tpk[2 * kk][0], Tpk[2 * kk][1],
                                  Tpk[2 * kk + 1][0], Tpk[2 * kk + 1][1]};
                mma_bf16(osum, pa, ONES2, ONES2);
                #pragma unroll
                for (int p = 0; p < 4; p++) {
                    uint32_t t[4]; ldbB(t, Vb, p, 2 * h32 + kk, lane);
                    mma_bf16(o[2 * p], pa, t[0], t[1]);
                    mma_bf16(o[2 * p + 1], pa, t[2], t[3]);
                }
            }
        }
    }

    float iA = 1.f / ((float)(rA + 1) + osum[0]);
    float iB = 1.f / ((float)(rA + 9) + osum[2]);
    const float* vA = g_vcs + (h * SQ + rA) * HD;
    const float* vB = vA + 8 * HD;
    int oc = h * 64 + pc;
    #pragma unroll
    for (int n = 0; n < 8; n++) {
        float2 cA = *(const float2*)&vA[n * 8 + pc];
        float2 cB = *(const float2*)&vB[n * 8 + pc];
        float f0 = (o[n][0] + cA.x) * iA, f1 = (o[n][1] + cA.y) * iA;
        float f2 = (o[n][2] + cB.x) * iB, f3 = (o[n][3] + cB.y) * iB;
        float h0 = bf_of(f0), h1 = bf_of(f1), h2 = bf_of(f2), h3 = bf_of(f3);
        g_aHb[(rA * EMB + oc + n * 8) >> 1]       = pkbf(h0, h1);
        g_aHb[((rA + 8) * EMB + oc + n * 8) >> 1] = pkbf(h2, h3);
        g_aLb[(rA * EMB + oc + n * 8) >> 1]       = pkbf(f0 - h0, f1 - h1);
        g_aLb[((rA + 8) * EMB + oc + n * 8) >> 1] = pkbf(f2 - h2, f3 - h3);
    }
}

// ---------------- kernel 3: output projection, k=32 chunks, 3 CTAs/SM ----------------
// per buffer bytes (stride 80): AH 0 | AL 10240 | BH 20480 | BL 25600; buf 30720; x2
#define PST 80
#define PBUF 30720
#define PROJ_SMEM (2 * PBUF)
__global__ void __launch_bounds__(256, 3) proj_kernel(float* __restrict__ out) {
    extern __shared__ char smc[];
    uint32_t smb = s2u(smc);
    int tid = threadIdx.x, wid = tid >> 5, lane = tid & 31;
    int s0 = blockIdx.x * 128, o0 = blockIdx.y * 64;
    float o[8][4] = {};

    {   // preload chunk 0 (k=32: A rows 64B, B rows 64B)
        #pragma unroll
        for (int i = 0; i < 2; i++) {
            int idx = tid + 256 * i, row = idx >> 2, c16 = idx & 3;
            uint32_t off = row * PST + c16 * 16;
            CP16(smb + off, (const char*)g_aHb + (size_t)(s0 + row) * EMB * 2 + c16 * 16);
            CP16(smb + 10240 + off, (const char*)g_aLb + (size_t)(s0 + row) * EMB * 2 + c16 * 16);
        }
        {
            int idx = tid, row = idx >> 2, c16 = idx & 3;
            uint32_t off = row * PST + c16 * 16;
            CP16(smb + 20480 + off, (const char*)g_woHb + (size_t)(o0 + row) * EMB * 2 + c16 * 16);
            CP16(smb + 25600 + off, (const char*)g_woLb + (size_t)(o0 + row) * EMB * 2 + c16 * 16);
        }
        CPCOMMIT();
    }

    for (int ch = 0; ch < 32; ch++) {
        int cur = ch & 1;
        CPWAIT0();
        __syncthreads();
        if (ch < 31) {
            int e0 = (ch + 1) * 32;
            uint32_t bb = smb + (uint32_t)((1 - cur) * PBUF);
            #pragma unroll
            for (int i = 0; i < 2; i++) {
                int idx = tid + 256 * i, row = idx >> 2, c16 = idx & 3;
                uint32_t off = row * PST + c16 * 16;
                CP16(bb + off, (const char*)g_aHb + ((size_t)(s0 + row) * EMB + e0) * 2 + c16 * 16);
                CP16(bb + 10240 + off, (const char*)g_aLb + ((size_t)(s0 + row) * EMB + e0) * 2 + c16 * 16);
            }
            {
                int idx = tid, row = idx >> 2, c16 = idx & 3;
                uint32_t off = row * PST + c16 * 16;
                CP16(bb + 20480 + off, (const char*)g_woHb + ((size_t)(o0 + row) * EMB + e0) * 2 + c16 * 16);
                CP16(bb + 25600 + off, (const char*)g_woLb + ((size_t)(o0 + row) * EMB + e0) * 2 + c16 * 16);
            }
            CPCOMMIT();
        }

        uint32_t base = smb + (uint32_t)(cur * PBUF);
        uint32_t AHb = base, ALb = base + 10240, BHb = base + 20480, BLb = base + 25600;
        #pragma unroll
        for (int ks = 0; ks < 2; ks++) {
            uint32_t ah[4], al[4];
            ldaS(ah, AHb, wid * 16, ks, lane, PST);
            ldaS(al, ALb, wid * 16, ks, lane, PST);
            #pragma unroll
            for (int p = 0; p < 4; p++) {
                uint32_t t[4];
                ldbS(t, BHb, p, ks, lane, PST);
                mma_bf16(o[2 * p], ah, t[0], t[1]); mma_bf16(o[2 * p + 1], ah, t[2], t[3]);
                mma_bf16(o[2 * p], al, t[0], t[1]); mma_bf16(o[2 * p + 1], al, t[2], t[3]);
                ldbS(t, BLb, p, ks, lane, PST);
                mma_bf16(o[2 * p], ah, t[0], t[1]); mma_bf16(o[2 * p + 1], ah, t[2], t[3]);
            }
        }
    }

    int r = wid * 16 + (lane >> 2), c = 2 * (lane & 3);
    #pragma unroll
    for (int n = 0; n < 8; n++) {
        *(float2*)&out[(s0 + r) * EMB + o0 + n * 8 + c]     = make_float2(o[n][0], o[n][1]);
        *(float2*)&out[(s0 + r + 8) * EMB + o0 + n * 8 + c] = make_float2(o[n][2], o[n][3]);
    }
}

// ---------------- launch ----------------
extern "C" void kernel_launch(void* const* d_in, const int* in_sizes, int n_in,
                              void* d_out, int out_size) {
    const float* x  = (const float*)d_in[0];
    const float* wq = (const float*)d_in[1];
    const float* wk = (const float*)d_in[2];
    const float* wv = (const float*)d_in[3];
    const float* wo = (const float*)d_in[4];
    float* out = (float*)d_out;
    (void)in_sizes; (void)n_in; (void)out_size;

    cudaFuncSetAttribute(qkv_kernel,   cudaFuncAttributeMaxDynamicSharedMemorySize, QKV_SMEM);
    cudaFuncSetAttribute(flash_kernel, cudaFuncAttributeMaxDynamicSharedMemorySize, FLASH_SMEM);
    cudaFuncSetAttribute(proj_kernel,  cudaFuncAttributeMaxDynamicSharedMemorySize, PROJ_SMEM);

    wo_split_kernel<<<EMB * EMB / 512, 256>>>(wo);
    qkv_kernel  <<<dim3(SQ / 128, NH, 3), 256, QKV_SMEM>>>(x, wq, wk, wv);
    vcs_kernel  <<<256, 256>>>();
    flash_kernel<<<dim3(SQ / 128, NH),    256, FLASH_SMEM>>>();
    proj_kernel <<<dim3(SQ / 128, EMB / 64), 256, PROJ_SMEM>>>(out);
}

// round 15
// speedup vs baseline: 1.0506x; 1.0506x over previous
#include <cuda_runtime.h>
#include <cstdint>

#define SQ   4096
#define EMB  1024
#define NH   16
#define HD   64

// ---------------- scratch ----------------
__device__ uint32_t g_qb [NH*SQ*HD/2];   // bf16 [h][s][d]
__device__ uint32_t g_kb [NH*SQ*HD/2];   // bf16 [h][s][d]
__device__ uint32_t g_vb [NH*HD*SQ/2];   // bf16 [h][d][s]
__device__ float    g_vF [NH*SQ*HD];     // fp32 exact V [h][s][d]
__device__ float    g_cs [NH*64*HD];     // per-64-block V colsums
__device__ float    g_vcs[NH*SQ*HD];     // inclusive cumsum over keys
__device__ uint32_t g_aHb[SQ*EMB/2];     // attention out bf16 hi
__device__ uint32_t g_aLb[SQ*EMB/2];     // attention out bf16 lo
__device__ uint32_t g_woHb[EMB*EMB/2];
__device__ uint32_t g_woLb[EMB*EMB/2];

// ---------------- helpers ----------------
__device__ __forceinline__ uint32_t s2u(const void* p) {
    uint32_t a; asm("{ .reg .u64 t; cvta.to.shared.u64 t, %1; cvt.u32.u64 %0, t; }" : "=r"(a) : "l"(p));
    return a;
}
__device__ __forceinline__ uint32_t pkbf(float lo, float hi) {   // packed bf16x2 {lo|hi<<16}
    uint32_t r; asm("cvt.rn.bf16x2.f32 %0, %1, %2;" : "=r"(r) : "f"(hi), "f"(lo));
    return r;
}
__device__ __forceinline__ float bf_of(float f) {
    uint32_t r; asm("cvt.rn.bf16x2.f32 %0, %1, %2;" : "=r"(r) : "f"(0.f), "f"(f));
    return __uint_as_float(r << 16);
}
__device__ __forceinline__ void ldm4(uint32_t r[4], uint32_t a) {
    asm volatile("ldmatrix.sync.aligned.m8n8.x4.shared.b16 {%0,%1,%2,%3}, [%4];"
                 : "=r"(r[0]), "=r"(r[1]), "=r"(r[2]), "=r"(r[3]) : "r"(a));
}
__device__ __forceinline__ void mma_bf16(float d[4], const uint32_t a[4], uint32_t b0, uint32_t b1) {
    asm volatile("mma.sync.aligned.m16n8k16.row.col.f32.bf16.bf16.f32 "
                 "{%0,%1,%2,%3},{%4,%5,%6,%7},{%8,%9},{%0,%1,%2,%3};"
                 : "+f"(d[0]), "+f"(d[1]), "+f"(d[2]), "+f"(d[3])
                 : "r"(a[0]), "r"(a[1]), "r"(a[2]), "r"(a[3]), "r"(b0), "r"(b1));
}
#define CP16(d_, s_) asm volatile("cp.async.cg.shared.global [%0], [%1], 16;" :: "r"(d_), "l"(s_))
#define CPCOMMIT()   asm volatile("cp.async.commit_group;" ::: "memory")
#define CPWAIT0()    asm volatile("cp.async.wait_group 0;" ::: "memory")

// bf16 fragment loads, parametric row stride (16B-aligned, conflict-free)
__device__ __forceinline__ void ldaS(uint32_t r[4], uint32_t base, int m0, int ks, int lane, int st) {
    int g = lane >> 3, rr = lane & 7;
    uint32_t a = base + (uint32_t)(m0 + ((g & 1) << 3) + rr) * st + (uint32_t)((ks << 4) + ((g >> 1) << 3)) * 2;
    ldm4(r, a);
}
__device__ __forceinline__ void ldbS(uint32_t t[4], uint32_t base, int p, int ks, int lane, int st) {
    int g = lane >> 3, rr = lane & 7;
    uint32_t a = base + (uint32_t)(p * 16 + ((g >> 1) << 3) + rr) * st + (uint32_t)((ks << 4) + ((g & 1) << 3)) * 2;
    ldm4(t, a);
}
#define BST 144
#define ldaB(r, base, m0, ks, lane) ldaS(r, base, m0, ks, lane, BST)
#define ldbB(t, base, p, ks, lane)  ldbS(t, base, p, ks, lane, BST)

// ---------------- kernel 0: split wo into bf16 hi/lo ----------------
__global__ void wo_split_kernel(const float* __restrict__ wo) {
    int i = blockIdx.x * 256 + threadIdx.x;
    float2 w = *(const float2*)&wo[2 * i];
    float h0 = bf_of(w.x), h1 = bf_of(w.y);
    g_woHb[i] = pkbf(h0, h1);
    g_woLb[i] = pkbf(w.x - h0, w.y - h1);
}

// ---------------- kernel 0b: inclusive cumsum of V over keys (ILP) ----------------
__global__ void vcs_kernel() {
    int idx = blockIdx.x * 256 + threadIdx.x;   // h(16) x blk(64) x d(64)
    int d = idx & 63, blk = (idx >> 6) & 63, h = idx >> 12;
    float p0 = 0.f, p1 = 0.f, p2 = 0.f, p3 = 0.f;
    const float* cs = g_cs + (h * 64) * HD + d;
    int b = 0;
    for (; b + 4 <= blk; b += 4) {
        p0 += cs[b * HD]; p1 += cs[(b + 1) * HD];
        p2 += cs[(b + 2) * HD]; p3 += cs[(b + 3) * HD];
    }
    for (; b < blk; b++) p0 += cs[b * HD];
    float run = (p0 + p1) + (p2 + p3);
    int base = (h * SQ + blk * 64) * HD + d;
    #pragma unroll
    for (int c = 0; c < 64; c += 16) {
        float v[16];
        #pragma unroll
        for (int r = 0; r < 16; r++) v[r] = g_vF[base + (c + r) * HD];
        #pragma unroll
        for (int r = 0; r < 16; r++) { run += v[r]; g_vcs[base + (c + r) * HD] = run; }
    }
}

// ---------------- kernel 1: QKV projection, all bf16, 3 CTAs/SM ----------------
#define QKV_SMEM 55296
__global__ void __launch_bounds__(256, 3) qkv_kernel(
    const float* __restrict__ x,
    const float* __restrict__ wq, const float* __restrict__ wk, const float* __restrict__ wv)
{
    extern __shared__ char smc[];
    uint32_t smb = s2u(smc);
    uint32_t XhB = smb, XlB = smb + 18432, WhB = smb + 36864, WlB = smb + 46080;
    int tid = threadIdx.x, wid = tid >> 5, lane = tid & 31;
    int bx = blockIdx.x, s0 = bx * 128, h = blockIdx.y, m = blockIdx.z;
    const float* w = (m == 0 ? wq : (m == 1 ? wk : wv)) + h * 64 * 64;

    #pragma unroll
    for (int i = 0; i < 8; i++) {
        int idx = tid + 256 * i, row = idx >> 4, c4 = idx & 15;
        float4 v = *(const float4*)&x[(s0 + row) * EMB + h * 64 + c4 * 4];
        float h0 = bf_of(v.x), h1 = bf_of(v.y), h2 = bf_of(v.z), h3 = bf_of(v.w);
        *(uint2*)(smc + row * BST + c4 * 8) = make_uint2(pkbf(h0, h1), pkbf(h2, h3));
        if (m == 2)
            *(uint2*)(smc + 18432 + row * BST + c4 * 8) =
                make_uint2(pkbf(v.x - h0, v.y - h1), pkbf(v.z - h2, v.w - h3));
    }
    #pragma unroll
    for (int i = 0; i < 4; i++) {
        int idx = tid + 256 * i, row = idx >> 4, c4 = idx & 15;
        float4 v = *(const float4*)&w[row * 64 + c4 * 4];
        float h0 = bf_of(v.x), h1 = bf_of(v.y), h2 = bf_of(v.z), h3 = bf_of(v.w);
        *(uint2*)(smc + 36864 + row * BST + c4 * 8) = make_uint2(pkbf(h0, h1), pkbf(h2, h3));
        if (m == 2)
            *(uint2*)(smc + 46080 + row * BST + c4 * 8) =
                make_uint2(pkbf(v.x - h0, v.y - h1), pkbf(v.z - h2, v.w - h3));
    }
    __syncthreads();

    float o[8][4] = {};
    #pragma unroll
    for (int ks = 0; ks < 4; ks++) {
        uint32_t aa[4]; ldaB(aa, XhB, wid * 16, ks, lane);
        #pragma unroll
        for (int p = 0; p < 4; p++) {
            uint32_t t[4]; ldbB(t, WhB, p, ks, lane);
            mma_bf16(o[2 * p], aa, t[0], t[1]); mma_bf16(o[2 * p + 1], aa, t[2], t[3]);
        }
    }
    if (m == 2) {
        #pragma unroll
        for (int ks = 0; ks < 4; ks++) {
            uint32_t aa[4]; ldaB(aa, XlB, wid * 16, ks, lane);
            #pragma unroll
            for (int p = 0; p < 4; p++) {
                uint32_t t[4]; ldbB(t, WhB, p, ks, lane);
                mma_bf16(o[2 * p], aa, t[0], t[1]); mma_bf16(o[2 * p + 1], aa, t[2], t[3]);
            }
        }
        #pragma unroll
        for (int ks = 0; ks < 4; ks++) {
            uint32_t aa[4]; ldaB(aa, XhB, wid * 16, ks, lane);
            #pragma unroll
            for (int p = 0; p < 4; p++) {
                uint32_t t[4]; ldbB(t, WlB, p, ks, lane);
                mma_bf16(o[2 * p], aa, t[0], t[1]); mma_bf16(o[2 * p + 1], aa, t[2], t[3]);
            }
        }
    }

    int r = wid * 16 + (lane >> 2), c = 2 * (lane & 3);
    if (m < 2) {
        uint32_t* dst = (m == 0 ? g_qb : g_kb) + ((h * SQ + s0) * HD >> 1);
        #pragma unroll
        for (int n = 0; n < 8; n++) {
            dst[(r * HD + n * 8 + c) >> 1]       = pkbf(o[n][0], o[n][1]);
            dst[((r + 8) * HD + n * 8 + c) >> 1] = pkbf(o[n][2], o[n][3]);
        }
    } else {
        #pragma unroll
        for (int n = 0; n < 8; n++) {
            *(float2*)&g_vF[(h * SQ + s0 + r) * HD + n * 8 + c]     = make_float2(o[n][0], o[n][1]);
            *(float2*)&g_vF[(h * SQ + s0 + r + 8) * HD + n * 8 + c] = make_float2(o[n][2], o[n][3]);
        }
        __syncthreads();
        float* Vt = (float*)smc;   // [d][s], stride 132 floats
        #pragma unroll
        for (int n = 0; n < 8; n++) {
            #pragma unroll
            for (int j = 0; j < 4; j++) {
                int d = n * 8 + c + (j & 1), rr = r + ((j >> 1) << 3);
                Vt[d * 132 + rr] = o[n][j];
            }
        }
        __syncthreads();
        #pragma unroll
        for (int i = 0; i < 8; i++) {
            int idx = tid + 256 * i, d = idx >> 5, s4 = idx & 31;
            float4 v = *(float4*)&Vt[d * 132 + s4 * 4];
            *(uint2*)&g_vb[((h * HD + d) * SQ + s0 + s4 * 4) >> 1] =
                make_uint2(pkbf(v.x, v.y), pkbf(v.z, v.w));
        }
        {
            int d = tid >> 2, half = (tid >> 1) & 1, part = tid & 1;
            int sb = half * 64 + part * 32;
            float cs = 0.f;
            #pragma unroll
            for (int j = 0; j < 32; j += 4) {
                float4 a4 = *(float4*)&Vt[d * 132 + sb + j];
                cs += a4.x + a4.y + a4.z + a4.w;
            }
            cs += __shfl_xor_sync(0xffffffffu, cs, 1);
            if (part == 0) g_cs[(h * 64 + bx * 2 + half) * HD + d] = cs;
        }
    }
}

// ---------------- kernel 2: flash attention (unchanged from R13) ----------------
#define F_K0 18432
#define F_V0 36864
#define FLASH_SMEM 55296
#define ONES2 0x3F803F80u
#define C1X2  0x3E003E00u
#define C2X2  0x3C003C00u
__global__ void __launch_bounds__(256, 3) flash_kernel() {
    extern __shared__ char smc[];
    uint32_t smb = s2u(smc);
    int tid = threadIdx.x, wid = tid >> 5, lane = tid & 31;
    int qb = 31 - (int)blockIdx.x;
    int h = blockIdx.y;
    int kb_last = 2 * qb + 1;
    int s0 = qb * 128;

    {
        const uint4* qs = (const uint4*)(g_qb + ((h * SQ + s0) * HD >> 1));
        #pragma unroll
        for (int i = 0; i < 4; i++) {
            int idx = tid + 256 * i, row = idx >> 3, c16 = idx & 7;
            *(uint4*)(smc + row * BST + c16 * 16) = qs[idx];
        }
    }
    {
        const char* kp = (const char*)g_kb + (size_t)(h * SQ) * HD * 2;
        const char* vp = (const char*)g_vb + (size_t)(h * HD) * SQ * 2;
        #pragma unroll
        for (int i = 0; i < 2; i++) {
            int idx = tid + 256 * i, row = idx >> 3, c16 = idx & 7;
            CP16(smb + F_K0 + row * BST + c16 * 16, kp + (size_t)row * HD * 2 + c16 * 16);
            CP16(smb + F_V0 + row * BST + c16 * 16, vp + (size_t)row * SQ * 2 + c16 * 16);
        }
        CPCOMMIT();
    }
    __syncthreads();

    uint32_t qa[4][4];
    #pragma unroll
    for (int ks = 0; ks < 4; ks++) ldaB(qa[ks], smb, wid * 16, ks, lane);

    float o[8][4] = {};
    float osum[4] = {};
    int pr = wid * 16 + (lane >> 2), pc = 2 * (lane & 3);
    int rA = s0 + pr;
    const float C1 = 0.125f, C2 = 0.0078125f;

    for (int kb = 0; kb <= kb_last; kb++) {
        int cur = kb & 1;
        CPWAIT0();
        __syncthreads();
        uint32_t Kb = smb + F_K0 + cur * 9216;
        uint32_t Vb = smb + F_V0 + cur * 9216;

        if (kb < kb_last) {
            int nb = kb + 1;
            const char* kp = (const char*)g_kb + (size_t)(h * SQ + nb * 64) * HD * 2;
            const char* vp = (const char*)g_vb + ((size_t)(h * HD) * SQ + nb * 64) * 2;
            uint32_t dk = smb + F_K0 + (1 - cur) * 9216;
            uint32_t dv = smb + F_V0 + (1 - cur) * 9216;
            #pragma unroll
            for (int i = 0; i < 2; i++) {
                int idx = tid + 256 * i, row = idx >> 3, c16 = idx & 7;
                CP16(dk + row * BST + c16 * 16, kp + (size_t)row * HD * 2 + c16 * 16);
                CP16(dv + row * BST + c16 * 16, vp + (size_t)row * SQ * 2 + c16 * 16);
            }
            CPCOMMIT();
        }

        bool diag = (kb >= 2 * qb);
        #pragma unroll
        for (int h32 = 0; h32 < 2; h32++) {
            float s[4][4] = {};
            #pragma unroll
            for (int ks = 0; ks < 4; ks++) {
                #pragma unroll
                for (int pp = 0; pp < 2; pp++) {
                    uint32_t t[4]; ldbB(t, Kb, 2 * h32 + pp, ks, lane);
                    mma_bf16(s[2 * pp], qa[ks], t[0], t[1]);
                    mma_bf16(s[2 * pp + 1], qa[ks], t[2], t[3]);
                }
            }
            uint32_t Tpk[4][2];
            if (diag) {
                #pragma unroll
                for (int n = 0; n < 4; n++) {
                    #pragma unroll
                    for (int j = 0; j < 4; j++) {
                        float sv = s[n][j];
                        float T = sv * fmaf(sv, C2, C1);
                        int col = kb * 64 + h32 * 32 + n * 8 + pc + (j & 1);
                        int row = rA + ((j >> 1) << 3);
                        s[n][j] = (col <= row) ? T : 0.f;
                    }
                    Tpk[n][0] = pkbf(s[n][0], s[n][1]);
                    Tpk[n][1] = pkbf(s[n][2], s[n][3]);
                }
            } else {
                #pragma unroll
                for (int n = 0; n < 4; n++) {
                    uint32_t s2a = pkbf(s[n][0], s[n][1]);
                    uint32_t s2b = pkbf(s[n][2], s[n][3]);
                    uint32_t ua, ub;
                    asm("fma.rn.bf16x2 %0, %1, %2, %3;" : "=r"(ua) : "r"(s2a), "r"(C2X2), "r"(C1X2));
                    asm("fma.rn.bf16x2 %0, %1, %2, %3;" : "=r"(ub) : "r"(s2b), "r"(C2X2), "r"(C1X2));
                    asm("mul.rn.bf16x2 %0, %1, %2;" : "=r"(Tpk[n][0]) : "r"(s2a), "r"(ua));
                    asm("mul.rn.bf16x2 %0, %1, %2;" : "=r"(Tpk[n][1]) : "r"(s2b), "r"(ub));
                }
            }
            #pragma unroll
            for (int kk = 0; kk < 2; kk++) {
                uint32_t pa[4] = {Tpk[2 * kk][0], Tpk[2 * kk][1],
                                  Tpk[2 * kk + 1][0], Tpk[2 * kk + 1][1]};
                mma_bf16(osum, pa, ONES2, ONES2);
                #pragma unroll
                for (int p = 0; p < 4; p++) {
                    uint32_t t[4]; ldbB(t, Vb, p, 2 * h32 + kk, lane);
                    mma_bf16(o[2 * p], pa, t[0], t[1]);
                    mma_bf16(o[2 * p + 1], pa, t[2], t[3]);
                }
            }
        }
    }

    float iA = 1.f / ((float)(rA + 1) + osum[0]);
    float iB = 1.f / ((float)(rA + 9) + osum[2]);
    const float* vA = g_vcs + (h * SQ + rA) * HD;
    const float* vB = vA + 8 * HD;
    int oc = h * 64 + pc;
    #pragma unroll
    for (int n = 0; n < 8; n++) {
        float2 cA = *(const float2*)&vA[n * 8 + pc];
        float2 cB = *(const float2*)&vB[n * 8 + pc];
        float f0 = (o[n][0] + cA.x) * iA, f1 = (o[n][1] + cA.y) * iA;
        float f2 = (o[n][2] + cB.x) * iB, f3 = (o[n][3] + cB.y) * iB;
        float h0 = bf_of(f0), h1 = bf_of(f1), h2 = bf_of(f2), h3 = bf_of(f3);
        g_aHb[(rA * EMB + oc + n * 8) >> 1]       = pkbf(h0, h1);
        g_aHb[((rA + 8) * EMB + oc + n * 8) >> 1] = pkbf(h2, h3);
        g_aLb[(rA * EMB + oc + n * 8) >> 1]       = pkbf(f0 - h0, f1 - h1);
        g_aLb[((rA + 8) * EMB + oc + n * 8) >> 1] = pkbf(f2 - h2, f3 - h3);
    }
}

// ---------------- kernel 3: output projection, 64x64 tiles, N-split warps, 4 CTAs/SM ----------------
// grid (64, 16). Warp: rows (wid&3)*16, cols (wid>>2)*32.
// per buffer (stride 80): AH 0 | AL 5120 | BH 10240 | BL 15360; buf 20480; x2 = 40KB
#define PST 80
#define PBUF 20480
#define PROJ_SMEM (2 * PBUF)
__global__ void __launch_bounds__(256, 4) proj_kernel(float* __restrict__ out) {
    extern __shared__ char smc[];
    uint32_t smb = s2u(smc);
    int tid = threadIdx.x, wid = tid >> 5, lane = tid & 31;
    int s0 = blockIdx.x * 64, o0 = blockIdx.y * 64;
    int m0 = (wid & 3) * 16, cg = wid >> 2;   // row group, col group
    float o[4][4] = {};

    {   // preload chunk 0: A 64 rows x 64B (hi+lo), B 64 rows x 64B (hi+lo)
        int row = tid >> 2, c16 = tid & 3;
        uint32_t off = row * PST + c16 * 16;
        size_t ga = ((size_t)(s0 + row) * EMB) * 2 + c16 * 16;
        size_t gb = ((size_t)(o0 + row) * EMB) * 2 + c16 * 16;
        CP16(smb + off,          (const char*)g_aHb  + ga);
        CP16(smb + 5120 + off,   (const char*)g_aLb  + ga);
        CP16(smb + 10240 + off,  (const char*)g_woHb + gb);
        CP16(smb + 15360 + off,  (const char*)g_woLb + gb);
        CPCOMMIT();
    }

    for (int ch = 0; ch < 32; ch++) {
        int cur = ch & 1;
        CPWAIT0();
        __syncthreads();
        if (ch < 31) {
            int e0 = (ch + 1) * 32;
            uint32_t bb = smb + (uint32_t)((1 - cur) * PBUF);
            int row = tid >> 2, c16 = tid & 3;
            uint32_t off = row * PST + c16 * 16;
            size_t ga = ((size_t)(s0 + row) * EMB + e0) * 2 + c16 * 16;
            size_t gb = ((size_t)(o0 + row) * EMB + e0) * 2 + c16 * 16;
            CP16(bb + off,          (const char*)g_aHb  + ga);
            CP16(bb + 5120 + off,   (const char*)g_aLb  + ga);
            CP16(bb + 10240 + off,  (const char*)g_woHb + gb);
            CP16(bb + 15360 + off,  (const char*)g_woLb + gb);
            CPCOMMIT();
        }

        uint32_t base = smb + (uint32_t)(cur * PBUF);
        uint32_t AHb = base, ALb = base + 5120, BHb = base + 10240, BLb = base + 15360;
        #pragma unroll
        for (int ks = 0; ks < 2; ks++) {
            uint32_t ah[4], al[4];
            ldaS(ah, AHb, m0, ks, lane, PST);
            ldaS(al, ALb, m0, ks, lane, PST);
            #pragma unroll
            for (int pp = 0; pp < 2; pp++) {
                int p = 2 * cg + pp;
                uint32_t t[4];
                ldbS(t, BHb, p, ks, lane, PST);
                mma_bf16(o[2 * pp], ah, t[0], t[1]); mma_bf16(o[2 * pp + 1], ah, t[2], t[3]);
                mma_bf16(o[2 * pp], al, t[0], t[1]); mma_bf16(o[2 * pp + 1], al, t[2], t[3]);
                ldbS(t, BLb, p, ks, lane, PST);
                mma_bf16(o[2 * pp], ah, t[0], t[1]); mma_bf16(o[2 * pp + 1], ah, t[2], t[3]);
            }
        }
    }

    int r = m0 + (lane >> 2), c = 2 * (lane & 3);
    int cb = o0 + cg * 32;
    #pragma unroll
    for (int n = 0; n < 4; n++) {
        *(float2*)&out[(s0 + r) * EMB + cb + n * 8 + c]     = make_float2(o[n][0], o[n][1]);
        *(float2*)&out[(s0 + r + 8) * EMB + cb + n * 8 + c] = make_float2(o[n][2], o[n][3]);
    }
}

// ---------------- launch ----------------
extern "C" void kernel_launch(void* const* d_in, const int* in_sizes, int n_in,
                              void* d_out, int out_size) {
    const float* x  = (const float*)d_in[0];
    const float* wq = (const float*)d_in[1];
    const float* wk = (const float*)d_in[2];
    const float* wv = (const float*)d_in[3];
    const float* wo = (const float*)d_in[4];
    float* out = (float*)d_out;
    (void)in_sizes; (void)n_in; (void)out_size;

    cudaFuncSetAttribute(qkv_kernel,   cudaFuncAttributeMaxDynamicSharedMemorySize, QKV_SMEM);
    cudaFuncSetAttribute(flash_kernel, cudaFuncAttributeMaxDynamicSharedMemorySize, FLASH_SMEM);
    cudaFuncSetAttribute(proj_kernel,  cudaFuncAttributeMaxDynamicSharedMemorySize, PROJ_SMEM);

    wo_split_kernel<<<EMB * EMB / 512, 256>>>(wo);
    qkv_kernel  <<<dim3(SQ / 128, NH, 3), 256, QKV_SMEM>>>(x, wq, wk, wv);
    vcs_kernel  <<<256, 256>>>();
    flash_kernel<<<dim3(SQ / 128, NH),    256, FLASH_SMEM>>>();
    proj_kernel <<<dim3(SQ / 64, EMB / 64), 256, PROJ_SMEM>>>(out);
}